// round 15
// baseline (speedup 1.0000x reference)
#include <cuda_runtime.h>
#include <cuda_fp16.h>
#include <cstdint>

// ---------------------------------------------------------------------------
// AdaptiveSoftmax — fp16 mma.sync, warp tile 64x64 (4 warps, 128 thr,
// block 128x128), fully-unrolled 3-slot cp.async ring, fused-CE epilogue.
//   0: w_in [4096,1024] f32   1: target [4096] i32
//   2: head_w [2002,1024] f32 3: head_b [2002] f32
//   4: tail0_w1 [1024,1024]   5: tail0_w2 [8000,1024]
//   6: tail1_w1 [256,1024]    7: tail1_w2 [40000,256]
//   out: scalar f32 loss
// ---------------------------------------------------------------------------

#define N_TOK 4096
#define PT_STRIDE 320   // >= 313 N-tiles (tail1, 128-wide)

// fp16 operands, kt32-tiled with PADDED row counts (R multiple of 128):
// u32 idx = ((kt*Rp + row)*16 + slot), slot(p) = (p&3)*4 + (p>>2).
__device__ __align__(16) uint32_t d_winh [2097152];   // 4096 x 1024
__device__ __align__(16) uint32_t d_hwh  [1048576];   // 2048(pad) x 1024
__device__ __align__(16) uint32_t d_t0w1h[524288];    // 1024 x 1024
__device__ __align__(16) uint32_t d_t0w2h[4128768];   // 8064(pad) x 1024
__device__ __align__(16) uint32_t d_t1w1h[131072];    // 256 x 1024
__device__ __align__(16) uint32_t d_t1w2h[5128192];   // 40064(pad) x 256
__device__ __align__(16) uint32_t d_h0h  [2097152];   // 4096 x 1024
__device__ __align__(16) uint32_t d_h1h  [524288];    // 4096 x 256

__device__ __align__(16) float2 d_part[(size_t)3 * N_TOK * PT_STRIDE];
__device__ float d_labv[3 * N_TOK];
__device__ float d_nllv[3 * N_TOK];
__device__ int   d_labh[N_TOK];
__device__ int   d_lab0[N_TOK];
__device__ int   d_lab1[N_TOK];
__device__ int   d_idx0[N_TOK];
__device__ int   d_idx1[N_TOK];
__device__ int   d_cnt0;
__device__ int   d_cnt1;

// ---------------------------------------------------------------------------
__global__ void init_kernel() {
    if (threadIdx.x == 0) { d_cnt0 = 0; d_cnt1 = 0; }
}

__global__ void gather_kernel(const int* __restrict__ target) {
    int i = blockIdx.x * blockDim.x + threadIdx.x;
    if (i >= N_TOK) return;
    int t = target[i];
    int labh = t;
    if (t >= 2000 && t < 10000) {
        labh = 2000;
        int p = atomicAdd(&d_cnt0, 1);
        if (p < N_TOK) { d_idx0[p] = i; d_lab0[p] = t - 2000; }
    } else if (t >= 10000 && t < 50000) {
        labh = 2001;
        int p = atomicAdd(&d_cnt1, 1);
        if (p < N_TOK) { d_idx1[p] = i; d_lab1[p] = t - 10000; }
    }
    d_labh[i] = min(max(labh, 0), 2001);
}

// ---------------------------------------------------------------------------
__device__ __forceinline__ uint32_t pack_h2(float x, float y) {
    __half2 h = __floats2half2_rn(x, y);
    return *reinterpret_cast<uint32_t*>(&h);
}

#define W0 524288
#define W1 256256
#define W2 131072
#define W3 1024000
#define W4 32768
#define W5 1280000
#define WTOT (W0+W1+W2+W3+W4+W5)

__global__ __launch_bounds__(256)
void convert_kernel(const float* __restrict__ w_in, const float* __restrict__ head_w,
                    const float* __restrict__ t0w1, const float* __restrict__ t0w2,
                    const float* __restrict__ t1w1, const float* __restrict__ t1w2) {
    int i = blockIdx.x * 256 + threadIdx.x;
    if (i >= WTOT) return;
    const float* src; uint32_t* dst; int R, RP, K, c = i;
    if (c < W0)              { src = w_in;   dst = d_winh;  R = 4096;  RP = 4096;  K = 1024; }
    else if ((c -= W0) < W1) { src = head_w; dst = d_hwh;   R = 2002;  RP = 2048;  K = 1024; }
    else if ((c -= W1) < W2) { src = t0w1;   dst = d_t0w1h; R = 1024;  RP = 1024;  K = 1024; }
    else if ((c -= W2) < W3) { src = t0w2;   dst = d_t0w2h; R = 8000;  RP = 8064;  K = 1024; }
    else if ((c -= W3) < W4) { src = t1w1;   dst = d_t1w1h; R = 256;   RP = 256;   K = 1024; }
    else      { c -= W4;       src = t1w2;   dst = d_t1w2h; R = 40000; RP = 40064; K = 256;  }
    int nrow4 = R * 4;
    int kt = c / nrow4;
    int rem = c - kt * nrow4;
    int r = rem >> 2, g = rem & 3;
    const float* s = src + (size_t)r * K + kt * 32 + 2 * g;
    uint4 o;
    o.x = pack_h2(s[0],  s[1]);
    o.y = pack_h2(s[8],  s[9]);
    o.z = pack_h2(s[16], s[17]);
    o.w = pack_h2(s[24], s[25]);
    reinterpret_cast<uint4*>(dst)[((size_t)kt * RP + r) * 4 + g] = o;
}

// ---------------------------------------------------------------------------
__device__ __forceinline__ void mma_f16(float* d, uint32_t a0, uint32_t a1,
                                        uint32_t a2, uint32_t a3,
                                        uint32_t b0, uint32_t b1) {
    asm volatile(
        "mma.sync.aligned.m16n8k16.row.col.f32.f16.f16.f32 "
        "{%0,%1,%2,%3}, {%4,%5,%6,%7}, {%8,%9}, {%0,%1,%2,%3};"
        : "+f"(d[0]), "+f"(d[1]), "+f"(d[2]), "+f"(d[3])
        : "r"(a0), "r"(a1), "r"(a2), "r"(a3), "r"(b0), "r"(b1));
}

template<int IMM>
__device__ __forceinline__ uint4 lds128i(uint32_t a) {
    uint4 v;
    asm volatile("ld.shared.v4.b32 {%0,%1,%2,%3}, [%4+%5];"
                 : "=r"(v.x), "=r"(v.y), "=r"(v.z), "=r"(v.w)
                 : "r"(a), "n"(IMM));
    return v;
}
template<int DOFF, int SOFF>
__device__ __forceinline__ void cp16i(uint32_t d, const uint32_t* g) {
    asm volatile("cp.async.cg.shared.global [%0+%2], [%1+%3], 16;"
                 :: "r"(d), "l"(g), "n"(DOFF), "n"(SOFF));
}
__device__ __forceinline__ void cp_commit() {
    asm volatile("cp.async.commit_group;" ::: "memory");
}
template<int G>
__device__ __forceinline__ void cp_waitg() {
    asm volatile("cp.async.wait_group %0;" :: "n"(G) : "memory");
}

__device__ __forceinline__ void ol_merge(float& mx, float& sm, float om, float os) {
    float nm = fmaxf(mx, om);
    sm = sm * __expf(mx - nm) + os * __expf(om - nm);
    mx = nm;
}

// ---------------------------------------------------------------------------
// Templated GEMM: block 128x128x32, 128 thr, 4 warps (2m x 2n), warp 64x64.
// Smem: 3 A slots (8KB @ s*8192) + 3 B slots (8KB @ 24576+s*8192) = 48KB.
// Fully unrolled mainloop: slots & offsets are compile-time literals.
// CFG: 0=head 1=t0s1 2=t1s1 3=t0s2 4=t1s2.
// CE spart aliases slot 0 (last tile in slot (NK-1)%3 = 1 for NK in {32,8}).
// ---------------------------------------------------------------------------
#define A_SLOT(S) ((S)*8192)
#define B_SLOT(S) (24576 + (S)*8192)

#define LOADT(S, U) do {                                                      \
    cp16i<A_SLOT(S)+0,    (U)*262144>(dst0, aP0);                             \
    cp16i<A_SLOT(S)+2048, (U)*262144>(dst0, aP1);                             \
    cp16i<A_SLOT(S)+4096, (U)*262144>(dst0, aP2);                             \
    cp16i<A_SLOT(S)+6144, (U)*262144>(dst0, aP3);                             \
    cp16i<B_SLOT(S)+0,    (U)*RB*64 + 0>(dst0, bP);                           \
    cp16i<B_SLOT(S)+2048, (U)*RB*64 + 2048>(dst0, bP);                        \
    cp16i<B_SLOT(S)+4096, (U)*RB*64 + 4096>(dst0, bP);                        \
    cp16i<B_SLOT(S)+6144, (U)*RB*64 + 6144>(dst0, bP);                        \
} while (0)

#define COMPUTE(S) do {                                                       \
    uint4 bf[8];                                                              \
    _Pragma("unroll")                                                         \
    for (int nt = 0; nt < 8; nt++) bf[nt] = lds128i<B_SLOT(S)>(bF[nt]);       \
    _Pragma("unroll")                                                         \
    for (int mt = 0; mt < 4; mt++) {                                          \
        uint4 lo = lds128i<A_SLOT(S)>(aF[mt][0]);                             \
        uint4 hi = lds128i<A_SLOT(S)>(aF[mt][1]);                             \
        _Pragma("unroll")                                                     \
        for (int nt = 0; nt < 8; nt++)                                        \
            mma_f16(acc[mt][nt], lo.x, hi.x, lo.y, hi.y, bf[nt].x, bf[nt].y); \
        _Pragma("unroll")                                                     \
        for (int nt = 0; nt < 8; nt++)                                        \
            mma_f16(acc[mt][nt], lo.z, hi.z, lo.w, hi.w, bf[nt].z, bf[nt].w); \
    }                                                                         \
} while (0)

// STEP(KT, U): KT = absolute k-tile (literal), U = in-chunk index (literal).
#define STEP(KT, U) do {                                                      \
    cp_waitg<1>(); __syncthreads();                                           \
    if ((KT) + 2 < NK) { LOADT(((KT)+2)%3, (U)+2); }                          \
    cp_commit();                                                              \
    COMPUTE((KT)%3);                                                          \
} while (0)

#define CHUNK(C) do {                                                         \
    STEP((C)*8+0, 0); STEP((C)*8+1, 1); STEP((C)*8+2, 2); STEP((C)*8+3, 3);   \
    STEP((C)*8+4, 4); STEP((C)*8+5, 5); STEP((C)*8+6, 6); STEP((C)*8+7, 7);   \
    aP0 += 524288; aP1 += 524288; aP2 += 524288; aP3 += 524288;               \
    bP  += (size_t)8 * RB * 16;                                               \
} while (0)

template<int CFG>
__global__ __launch_bounds__(128, 2)
void gemmT(const float* __restrict__ bias) {
    constexpr int N  = (CFG==0)?2002:(CFG==1)?1024:(CFG==2)?256:(CFG==3)?8000:40000;
    constexpr int RB = (CFG==0)?2048:(CFG==1)?1024:(CFG==2)?256:(CFG==3)?8064:40064;
    constexpr int K  = (CFG==4)?256:1024;
    constexpr int NK = K / 32;                 // 32 or 8
    constexpr bool CE = (CFG==0 || CFG==3 || CFG==4);
    constexpr int PH = (CFG==0)?0:(CFG==3)?1:2;

    const uint32_t* A  = (CFG<=2) ? d_winh : (CFG==3 ? d_h0h : d_h1h);
    const uint32_t* Bw = (CFG==0) ? d_hwh : (CFG==1) ? d_t0w1h :
                         (CFG==2) ? d_t1w1h : (CFG==3) ? d_t0w2h : d_t1w2h;
    uint32_t* Cout = (CFG==1) ? d_h0h : d_h1h;
    const int* idxArr = (CFG==1) ? d_idx0 : (CFG==2) ? d_idx1 : nullptr;
    const int* labArr = (CFG==0) ? d_labh : (CFG==3) ? d_lab0 : d_lab1;

    int cnt = (CFG==0) ? N_TOK : ((CFG==1 || CFG==3) ? d_cnt0 : d_cnt1);
    if (cnt > N_TOK) cnt = N_TOK;
    int m0 = blockIdx.y * 128;
    int n0 = blockIdx.x * 128;
    if (m0 >= cnt) return;

    __shared__ __align__(16) uint32_t Smem[12288];   // 48KB
    float2 (*spart)[2] = reinterpret_cast<float2(*)[2]>(Smem);  // aliases slot 0

    int tid  = threadIdx.x;
    int lane = tid & 31;
    int warp = tid >> 5;
    int wm = warp & 1;        // m offset wm*64
    int wn = warp >> 1;       // n offset wn*64

    uint32_t smemBase = (uint32_t)__cvta_generic_to_shared(Smem);

    // ---- loader mapping: row0 = tid>>2 (0..31), rows row0+32p, g = tid&3 ----
    int row0 = tid >> 2;
    int g    = tid & 3;
    uint32_t dst0 = smemBase + ((row0 * 16 + 4 * (g ^ ((row0 >> 1) & 3))) << 2);

    const uint32_t *aP0, *aP1, *aP2, *aP3;
    {
        const uint32_t* ap[4];
#pragma unroll
        for (int p = 0; p < 4; p++) {
            int am = m0 + row0 + 32 * p;
            int arow = (am < cnt) ? (idxArr ? idxArr[am] : am) : 0;
            arow = min(max(arow, 0), N_TOK - 1);
            ap[p] = A + (size_t)arow * 16 + 4 * g;
        }
        aP0 = ap[0]; aP1 = ap[1]; aP2 = ap[2]; aP3 = ap[3];
    }
    const uint32_t* bP = Bw + (size_t)(n0 + row0) * 16 + 4 * g;  // RB-padded

    // ---- fragment base addresses ----
    int gq = lane >> 2;
    int tq = lane & 3;
    uint32_t aF[4][2], bF[8];
#pragma unroll
    for (int mt = 0; mt < 4; mt++) {
        int ra = wm * 64 + mt * 16 + gq;
        aF[mt][0] = smemBase + ((ra * 16 + 4 * (tq ^ ((ra >> 1) & 3))) << 2);
        int rh = ra + 8;
        aF[mt][1] = smemBase + ((rh * 16 + 4 * (tq ^ ((rh >> 1) & 3))) << 2);
    }
#pragma unroll
    for (int nt = 0; nt < 8; nt++) {
        int rb = wn * 64 + nt * 8 + gq;
        bF[nt] = smemBase + ((rb * 16 + 4 * (tq ^ ((rb >> 1) & 3))) << 2);
    }

    float acc[4][8][4];
#pragma unroll
    for (int mt = 0; mt < 4; mt++)
#pragma unroll
        for (int nt = 0; nt < 8; nt++)
#pragma unroll
            for (int e = 0; e < 4; e++) acc[mt][nt][e] = 0.0f;

    // ---- prologue: tiles 0,1 -> slots 0,1 ----
    LOADT(0, 0); cp_commit();
    LOADT(1, 1); cp_commit();

    if constexpr (NK == 32) { CHUNK(0); CHUNK(1); CHUNK(2); CHUNK(3); }
    else                    { CHUNK(0); }

    if constexpr (CE) {
        float* labv = d_labv + PH * N_TOK;
#pragma unroll
        for (int mt = 0; mt < 4; mt++) {
#pragma unroll
            for (int h = 0; h < 2; h++) {
                int rloc = wm * 64 + mt * 16 + gq + h * 8;
                int m = m0 + rloc;
                bool ok = (m < cnt);
                int lab = ok ? labArr[m] : -1;
                float mx = -1e30f, sm = 0.f;
#pragma unroll
                for (int nt = 0; nt < 8; nt++) {
#pragma unroll
                    for (int e = 0; e < 2; e++) {
                        int col = n0 + wn * 64 + nt * 8 + tq * 2 + e;
                        if (col < N) {
                            float v = acc[mt][nt][h * 2 + e];
                            if (CFG == 0) v += bias[col];
                            mx = fmaxf(mx, v);
                        }
                    }
                }
#pragma unroll
                for (int nt = 0; nt < 8; nt++) {
#pragma unroll
                    for (int e = 0; e < 2; e++) {
                        int col = n0 + wn * 64 + nt * 8 + tq * 2 + e;
                        if (col < N) {
                            float v = acc[mt][nt][h * 2 + e];
                            if (CFG == 0) v += bias[col];
                            sm += __expf(v - mx);
                            if (ok && col == lab) labv[m] = v;
                        }
                    }
                }
#pragma unroll
                for (int off = 1; off <= 2; off <<= 1) {
                    float om = __shfl_xor_sync(0xffffffff, mx, off);
                    float os = __shfl_xor_sync(0xffffffff, sm, off);
                    ol_merge(mx, sm, om, os);
                }
                if (tq == 0) spart[rloc][wn] = make_float2(mx, sm);
            }
        }
        __syncthreads();
        if (tid < 128) {
            float mx = -1e30f, sm = 0.f;
#pragma unroll
            for (int w = 0; w < 2; w++) {
                float2 p = spart[tid][w];
                ol_merge(mx, sm, p.x, p.y);
            }
            int m = m0 + tid;
            if (m < cnt)
                d_part[((size_t)PH * N_TOK + m) * PT_STRIDE + blockIdx.x] =
                    make_float2(mx, sm);
        }
    } else {
        // ---- plain epilogue: write h in kt32-tiled fp16 layout (R=4096) ----
#pragma unroll
        for (int mt = 0; mt < 4; mt++) {
#pragma unroll
            for (int h = 0; h < 2; h++) {
                int r = m0 + wm * 64 + mt * 16 + gq + h * 8;
                if (r >= cnt) continue;
#pragma unroll
                for (int nt = 0; nt < 8; nt++) {
                    int cb = n0 + wn * 64 + nt * 8 + tq * 2;
                    if (cb < N) {
                        int kt = cb >> 5;
                        int p  = (cb & 31) >> 1;
                        int s  = (p & 3) * 4 + (p >> 2);
                        Cout[((size_t)kt * 4096 + r) * 16 + s] =
                            pack_h2(acc[mt][nt][h * 2 + 0], acc[mt][nt][h * 2 + 1]);
                    }
                }
            }
        }
    }
}

// ---------------------------------------------------------------------------
__global__ __launch_bounds__(32)
void ce_merge() {
    int phase = blockIdx.y;
    int ntiles = (phase == 0) ? 16 : ((phase == 1) ? 63 : 313);
    int cnt    = (phase == 0) ? N_TOK : ((phase == 1) ? d_cnt0 : d_cnt1);
    if (cnt > N_TOK) cnt = N_TOK;
    int b = blockIdx.x;
    if (b >= cnt) return;
    int lane = threadIdx.x;

    const float2* base = d_part + ((size_t)phase * N_TOK + b) * PT_STRIDE;
    float mx = -1e30f, sm = 0.f;
    for (int t = lane; t < ntiles; t += 32) {
        float2 p = base[t];
        ol_merge(mx, sm, p.x, p.y);
    }
#pragma unroll
    for (int off = 16; off > 0; off >>= 1) {
        float om = __shfl_xor_sync(0xffffffff, mx, off);
        float os = __shfl_xor_sync(0xffffffff, sm, off);
        ol_merge(mx, sm, om, os);
    }
    if (lane == 0)
        d_nllv[phase * N_TOK + b] = logf(sm) + mx - d_labv[phase * N_TOK + b];
}

__global__ __launch_bounds__(1024)
void reduce_kernel(float* __restrict__ out) {
    __shared__ double s[1024];
    int c0 = min(d_cnt0, N_TOK), c1 = min(d_cnt1, N_TOK);
    double a = 0.0;
    for (int i = threadIdx.x; i < N_TOK; i += 1024) a += (double)d_nllv[i];
    for (int i = threadIdx.x; i < c0;    i += 1024) a += (double)d_nllv[N_TOK + i];
    for (int i = threadIdx.x; i < c1;    i += 1024) a += (double)d_nllv[2 * N_TOK + i];
    s[threadIdx.x] = a;
    __syncthreads();
#pragma unroll
    for (int k = 512; k > 0; k >>= 1) {
        if (threadIdx.x < k) s[threadIdx.x] += s[threadIdx.x + k];
        __syncthreads();
    }
    if (threadIdx.x == 0) out[0] = (float)(s[0] / (double)N_TOK);
}

// ---------------------------------------------------------------------------
extern "C" void kernel_launch(void* const* d_in, const int* in_sizes, int n_in,
                              void* d_out, int out_size) {
    const float* w_in   = (const float*)d_in[0];
    const int*   target = (const int*)d_in[1];
    const float* head_w = (const float*)d_in[2];
    const float* head_b = (const float*)d_in[3];
    const float* t0w1   = (const float*)d_in[4];
    const float* t0w2   = (const float*)d_in[5];
    const float* t1w1   = (const float*)d_in[6];
    const float* t1w2   = (const float*)d_in[7];
    float* out = (float*)d_out;

    init_kernel<<<1, 32>>>();
    gather_kernel<<<(N_TOK + 255) / 256, 256>>>(target);
    convert_kernel<<<(WTOT + 255) / 256, 256>>>(w_in, head_w, t0w1, t0w2,
                                                t1w1, t1w2);

    gemmT<0><<<dim3(16, 32), 128>>>(head_b);    // head (fused CE, phase 0)
    gemmT<1><<<dim3(8, 32), 128>>>(nullptr);    // t0 stage1 -> d_h0h
    gemmT<2><<<dim3(2, 32), 128>>>(nullptr);    // t1 stage1 -> d_h1h
    gemmT<3><<<dim3(63, 32), 128>>>(nullptr);   // t0 logits (fused CE, ph 1)
    gemmT<4><<<dim3(313, 32), 128>>>(nullptr);  // t1 logits (fused CE, ph 2)

    ce_merge<<<dim3(N_TOK, 3), 32>>>();
    reduce_kernel<<<1, 1024>>>(out);
}

// round 16
// speedup vs baseline: 1.3583x; 1.3583x over previous
#include <cuda_runtime.h>
#include <cuda_fp16.h>
#include <cstdint>

// ---------------------------------------------------------------------------
// AdaptiveSoftmax — fp16 mma.sync, block 128x64 / warp 32x32, 4-slot cp.async
// ring (depth 3, x4-unrolled k-loop), hoisted fragment loads, fused-CE
// epilogue, merged launches.  (Recovery of round-12 best + LDS hoist.)
//   0: w_in [4096,1024] f32   1: target [4096] i32
//   2: head_w [2002,1024] f32 3: head_b [2002] f32
//   4: tail0_w1 [1024,1024]   5: tail0_w2 [8000,1024]
//   6: tail1_w1 [256,1024]    7: tail1_w2 [40000,256]
//   out: scalar f32 loss
// ---------------------------------------------------------------------------

#define N_TOK 4096
#define PT_STRIDE 632   // >= 625 N-tiles (tail1, 64-wide)

// fp16 operands in kt32-tiled layout: u32 idx = ((kt*R + row)*16 + slot)
// slot(p) = (p&3)*4 + (p>>2) for kpair p in k-tile of 32 halves.
__device__ __align__(16) uint32_t d_winh [2097152];
__device__ __align__(16) uint32_t d_hwh  [1025024];
__device__ __align__(16) uint32_t d_t0w1h[524288];
__device__ __align__(16) uint32_t d_t0w2h[4096000];
__device__ __align__(16) uint32_t d_t1w1h[131072];
__device__ __align__(16) uint32_t d_t1w2h[5120000];
__device__ __align__(16) uint32_t d_h0h  [2097152];   // R=4096, K=1024
__device__ __align__(16) uint32_t d_h1h  [524288];    // R=4096, K=256

__device__ __align__(16) float2 d_part[(size_t)3 * N_TOK * PT_STRIDE];
__device__ float d_labv[3 * N_TOK];
__device__ float d_nllv[3 * N_TOK];
__device__ int   d_labh[N_TOK];
__device__ int   d_lab0[N_TOK];
__device__ int   d_lab1[N_TOK];
__device__ int   d_idx0[N_TOK];
__device__ int   d_idx1[N_TOK];
__device__ int   d_cnt0;
__device__ int   d_cnt1;

// ---------------------------------------------------------------------------
__global__ void init_kernel() {
    if (threadIdx.x == 0) { d_cnt0 = 0; d_cnt1 = 0; }
}

__global__ void gather_kernel(const int* __restrict__ target) {
    int i = blockIdx.x * blockDim.x + threadIdx.x;
    if (i >= N_TOK) return;
    int t = target[i];
    int labh = t;
    if (t >= 2000 && t < 10000) {
        labh = 2000;
        int p = atomicAdd(&d_cnt0, 1);
        if (p < N_TOK) { d_idx0[p] = i; d_lab0[p] = t - 2000; }
    } else if (t >= 10000 && t < 50000) {
        labh = 2001;
        int p = atomicAdd(&d_cnt1, 1);
        if (p < N_TOK) { d_idx1[p] = i; d_lab1[p] = t - 10000; }
    }
    d_labh[i] = min(max(labh, 0), 2001);
}

// ---------------------------------------------------------------------------
__device__ __forceinline__ uint32_t pack_h2(float x, float y) {
    __half2 h = __floats2half2_rn(x, y);
    return *reinterpret_cast<uint32_t*>(&h);
}

#define W0 524288
#define W1 256256
#define W2 131072
#define W3 1024000
#define W4 32768
#define W5 1280000
#define WTOT (W0+W1+W2+W3+W4+W5)

__global__ __launch_bounds__(256)
void convert_kernel(const float* __restrict__ w_in, const float* __restrict__ head_w,
                    const float* __restrict__ t0w1, const float* __restrict__ t0w2,
                    const float* __restrict__ t1w1, const float* __restrict__ t1w2) {
    int i = blockIdx.x * 256 + threadIdx.x;
    if (i >= WTOT) return;
    const float* src; uint32_t* dst; int R, K, c = i;
    if (c < W0)              { src = w_in;   dst = d_winh;  R = 4096;  K = 1024; }
    else if ((c -= W0) < W1) { src = head_w; dst = d_hwh;   R = 2002;  K = 1024; }
    else if ((c -= W1) < W2) { src = t0w1;   dst = d_t0w1h; R = 1024;  K = 1024; }
    else if ((c -= W2) < W3) { src = t0w2;   dst = d_t0w2h; R = 8000;  K = 1024; }
    else if ((c -= W3) < W4) { src = t1w1;   dst = d_t1w1h; R = 256;   K = 1024; }
    else      { c -= W4;       src = t1w2;   dst = d_t1w2h; R = 40000; K = 256;  }
    int nrow4 = R * 4;
    int kt = c / nrow4;
    int rem = c - kt * nrow4;
    int r = rem >> 2, g = rem & 3;
    const float* s = src + (size_t)r * K + kt * 32 + 2 * g;
    uint4 o;
    o.x = pack_h2(s[0],  s[1]);
    o.y = pack_h2(s[8],  s[9]);
    o.z = pack_h2(s[16], s[17]);
    o.w = pack_h2(s[24], s[25]);
    reinterpret_cast<uint4*>(dst)[((size_t)kt * R + r) * 4 + g] = o;
}

// ---------------------------------------------------------------------------
__device__ __forceinline__ void mma_f16(float* d, uint32_t a0, uint32_t a1,
                                        uint32_t a2, uint32_t a3,
                                        uint32_t b0, uint32_t b1) {
    asm volatile(
        "mma.sync.aligned.m16n8k16.row.col.f32.f16.f16.f32 "
        "{%0,%1,%2,%3}, {%4,%5,%6,%7}, {%8,%9}, {%0,%1,%2,%3};"
        : "+f"(d[0]), "+f"(d[1]), "+f"(d[2]), "+f"(d[3])
        : "r"(a0), "r"(a1), "r"(a2), "r"(a3), "r"(b0), "r"(b1));
}

__device__ __forceinline__ void cp16(uint32_t saddr, const void* g) {
    asm volatile("cp.async.cg.shared.global [%0], [%1], 16;"
                 :: "r"(saddr), "l"(g));
}
__device__ __forceinline__ void cp_commit() {
    asm volatile("cp.async.commit_group;" ::: "memory");
}
__device__ __forceinline__ void cp_wait2() {
    asm volatile("cp.async.wait_group 2;" ::: "memory");
}

__device__ __forceinline__ void ol_merge(float& mx, float& sm, float om, float os) {
    float nm = fmaxf(mx, om);
    sm = sm * __expf(mx - nm) + os * __expf(om - nm);
    mx = nm;
}

// ---------------------------------------------------------------------------
// Unified GEMM: block 128x64x32, 256 thr, 8 warps (4m x 2n), warp 32x32.
// 4 x K32 slots (A: s*8192 B, B: 32768 + s*4096 B; 48KB), depth-3 prefetch
// (wait_group 2), one __syncthreads per k-tile, x4 unroll.
// All 8 fragment LDS.128 hoisted ahead of the 32 MMAs (one exposed latency).
// CE spart aliases slot 0 (last tile in slot 3).
// ---------------------------------------------------------------------------
__global__ __launch_bounds__(256, 3)
void gemm256(const float* __restrict__ bias, int stage) {
    int z = blockIdx.z;
    const uint32_t *A, *Bw;
    uint32_t* Cout = nullptr;
    const int* idxArr = nullptr;
    const int* labArr = nullptr;
    int N, K, cnt, xmax, ce = 0, phase = 0;
    bool useBias = false;
    if (stage == 0) {
        if (z == 0)      { A = d_winh; Bw = d_hwh;   N = 2002; K = 1024; cnt = N_TOK;
                           xmax = 32; ce = 1; phase = 0; labArr = d_labh; useBias = true; }
        else if (z == 1) { A = d_winh; Bw = d_t0w1h; N = 1024; K = 1024; cnt = d_cnt0;
                           xmax = 16; idxArr = d_idx0; Cout = d_h0h; }
        else             { A = d_winh; Bw = d_t1w1h; N = 256;  K = 1024; cnt = d_cnt1;
                           xmax = 4; idxArr = d_idx1; Cout = d_h1h; }
    } else {
        if (z == 0)      { A = d_h1h; Bw = d_t1w2h; N = 40000; K = 256;  cnt = d_cnt1;
                           xmax = 625; ce = 1; phase = 2; labArr = d_lab1; }
        else             { A = d_h0h; Bw = d_t0w2h; N = 8000;  K = 1024; cnt = d_cnt0;
                           xmax = 125; ce = 1; phase = 1; labArr = d_lab0; }
    }
    if ((int)blockIdx.x >= xmax) return;
    if (cnt > N_TOK) cnt = N_TOK;
    int m0 = blockIdx.y * 128;
    int n0 = blockIdx.x * 64;
    if (m0 >= cnt) return;

    // 4-slot ring: A slots 2048 u32 at [s*2048], B slots 1024 u32 at
    // [8192 + s*1024]. Total 12288 u32 = 48KB.
    __shared__ __align__(16) uint32_t Smem[12288];
    uint32_t* Ab = Smem;
    uint32_t* Bb = Smem + 8192;
    float2 (*spart)[2] = reinterpret_cast<float2(*)[2]>(Smem);  // aliases slot 0

    int tid  = threadIdx.x;
    int lane = tid & 31;
    int warp = tid >> 5;
    int wm = warp & 3;       // m offset wm*32
    int wn = warp >> 2;      // n offset wn*32

    // ---- A loader: 2 threads/row, 2 chunks each ----
    int lrow = tid >> 1;
    int hh   = tid & 1;
    int g0 = 2 * hh, g1 = 2 * hh + 1;
    int swzA = (lrow >> 1) & 3;
    uint32_t aShBase = (uint32_t)__cvta_generic_to_shared(Ab);
    uint32_t bShBase = (uint32_t)__cvta_generic_to_shared(Bb);
    uint32_t dA0 = (lrow * 16 + 4 * (g0 ^ swzA)) << 2;
    uint32_t dA1 = (lrow * 16 + 4 * (g1 ^ swzA)) << 2;
    // ---- B loader: 4 threads/row, 1 chunk each ----
    int brW = tid >> 2;
    int gB  = tid & 3;
    uint32_t dB = (brW * 16 + 4 * (gB ^ ((brW >> 1) & 3))) << 2;

    int am = m0 + lrow;
    int arow = (am < cnt) ? (idxArr ? idxArr[am] : am) : 0;
    arow = min(max(arow, 0), N_TOK - 1);
    int brow = min(n0 + brW, N - 1);

    float acc[2][4][4];
#pragma unroll
    for (int mt = 0; mt < 2; mt++)
#pragma unroll
        for (int nt = 0; nt < 4; nt++)
#pragma unroll
            for (int e = 0; e < 4; e++) acc[mt][nt][e] = 0.0f;

    int gq = lane >> 2;
    int tq = lane & 3;

    // ---- fragment base offsets (loop-invariant) ----
    uint32_t aOff[2][2], bOff[4];
#pragma unroll
    for (int mt = 0; mt < 2; mt++) {
        int ra = wm * 32 + mt * 16 + gq;
        aOff[mt][0] = (uint32_t)(ra * 16 + 4 * (tq ^ ((ra >> 1) & 3)));
        int rh = ra + 8;
        aOff[mt][1] = (uint32_t)(rh * 16 + 4 * (tq ^ ((rh >> 1) & 3)));
    }
#pragma unroll
    for (int nt = 0; nt < 4; nt++) {
        int rb = wn * 32 + nt * 8 + gq;
        bOff[nt] = (uint32_t)(rb * 16 + 4 * (tq ^ ((rb >> 1) & 3)));
    }

    int nk = K >> 5;
    const size_t aStep = 4096 * 16;
    const size_t bStep = (size_t)N * 16;
    const uint32_t* agp = A  + (size_t)arow * 16;
    const uint32_t* bgp = Bw + (size_t)brow * 16;

    // prologue: tiles 0,1,2 -> slots 0,1,2
#pragma unroll
    for (int p = 0; p < 3; p++) {
        uint32_t so = (uint32_t)p * 8192, sb = (uint32_t)p * 4096;
        cp16(aShBase + so + dA0, agp + 4 * g0);
        cp16(aShBase + so + dA1, agp + 4 * g1);
        cp16(bShBase + sb + dB,  bgp + 4 * gB);
        cp_commit();
        agp += aStep; bgp += bStep;
    }

    for (int kt0 = 0; kt0 < nk; kt0 += 4) {
#pragma unroll
        for (int u = 0; u < 4; u++) {
            int kt = kt0 + u;
            cp_wait2();
            __syncthreads();
            if (kt + 3 < nk) {
                uint32_t ns = (uint32_t)((u + 3) & 3);
                cp16(aShBase + ns * 8192 + dA0, agp + 4 * g0);
                cp16(aShBase + ns * 8192 + dA1, agp + 4 * g1);
                cp16(bShBase + ns * 4096 + dB,  bgp + 4 * gB);
                agp += aStep; bgp += bStep;
            }
            cp_commit();

            const uint32_t* As = Ab + u * 2048;   // compile-time slot
            const uint32_t* Bs = Bb + u * 1024;
            // ---- hoist ALL fragment loads before any MMA ----
            uint4 af[2][2], bf[4];
#pragma unroll
            for (int mt = 0; mt < 2; mt++) {
                af[mt][0] = *reinterpret_cast<const uint4*>(&As[aOff[mt][0]]);
                af[mt][1] = *reinterpret_cast<const uint4*>(&As[aOff[mt][1]]);
            }
#pragma unroll
            for (int nt = 0; nt < 4; nt++)
                bf[nt] = *reinterpret_cast<const uint4*>(&Bs[bOff[nt]]);
            // ---- 32 MMAs ----
#pragma unroll
            for (int mt = 0; mt < 2; mt++) {
#pragma unroll
                for (int nt = 0; nt < 4; nt++)
                    mma_f16(acc[mt][nt], af[mt][0].x, af[mt][1].x,
                            af[mt][0].y, af[mt][1].y, bf[nt].x, bf[nt].y);
#pragma unroll
                for (int nt = 0; nt < 4; nt++)
                    mma_f16(acc[mt][nt], af[mt][0].z, af[mt][1].z,
                            af[mt][0].w, af[mt][1].w, bf[nt].z, bf[nt].w);
            }
        }
    }

    if (ce) {
        // ---- fused CE epilogue ----
        float* labv = d_labv + phase * N_TOK;
#pragma unroll
        for (int mt = 0; mt < 2; mt++) {
#pragma unroll
            for (int h = 0; h < 2; h++) {
                int rloc = wm * 32 + mt * 16 + gq + h * 8;
                int m = m0 + rloc;
                bool ok = (m < cnt);
                int lab = ok ? labArr[m] : -1;
                float mx = -1e30f, sm = 0.f;
#pragma unroll
                for (int nt = 0; nt < 4; nt++) {
#pragma unroll
                    for (int e = 0; e < 2; e++) {
                        int col = n0 + wn * 32 + nt * 8 + tq * 2 + e;
                        if (col < N) {
                            float v = acc[mt][nt][h * 2 + e];
                            if (useBias) v += bias[col];
                            mx = fmaxf(mx, v);
                        }
                    }
                }
#pragma unroll
                for (int nt = 0; nt < 4; nt++) {
#pragma unroll
                    for (int e = 0; e < 2; e++) {
                        int col = n0 + wn * 32 + nt * 8 + tq * 2 + e;
                        if (col < N) {
                            float v = acc[mt][nt][h * 2 + e];
                            if (useBias) v += bias[col];
                            sm += __expf(v - mx);
                            if (ok && col == lab) labv[m] = v;
                        }
                    }
                }
#pragma unroll
                for (int off = 1; off <= 2; off <<= 1) {
                    float om = __shfl_xor_sync(0xffffffff, mx, off);
                    float os = __shfl_xor_sync(0xffffffff, sm, off);
                    ol_merge(mx, sm, om, os);
                }
                if (tq == 0) spart[rloc][wn] = make_float2(mx, sm);
            }
        }
        __syncthreads();
        if (tid < 128) {
            float mx = -1e30f, sm = 0.f;
#pragma unroll
            for (int w = 0; w < 2; w++) {
                float2 p = spart[tid][w];
                ol_merge(mx, sm, p.x, p.y);
            }
            int m = m0 + tid;
            if (m < cnt)
                d_part[((size_t)phase * N_TOK + m) * PT_STRIDE + blockIdx.x] =
                    make_float2(mx, sm);
        }
        return;
    }

    // ---- plain epilogue: write h in kt32-tiled fp16 layout ----
#pragma unroll
    for (int mt = 0; mt < 2; mt++) {
#pragma unroll
        for (int h = 0; h < 2; h++) {
            int r = m0 + wm * 32 + mt * 16 + gq + h * 8;
            if (r >= cnt) continue;
#pragma unroll
            for (int nt = 0; nt < 4; nt++) {
                int cb = n0 + wn * 32 + nt * 8 + tq * 2;
                int kt = cb >> 5;
                int p  = (cb & 31) >> 1;
                int s  = (p & 3) * 4 + (p >> 2);
                Cout[((size_t)kt * 4096 + r) * 16 + s] =
                    pack_h2(acc[mt][nt][h * 2 + 0], acc[mt][nt][h * 2 + 1]);
            }
        }
    }
}

// ---------------------------------------------------------------------------
__global__ __launch_bounds__(32)
void ce_merge() {
    int phase = blockIdx.y;
    int ntiles = (phase == 0) ? 32 : ((phase == 1) ? 125 : 625);
    int cnt    = (phase == 0) ? N_TOK : ((phase == 1) ? d_cnt0 : d_cnt1);
    if (cnt > N_TOK) cnt = N_TOK;
    int b = blockIdx.x;
    if (b >= cnt) return;
    int lane = threadIdx.x;

    const float2* base = d_part + ((size_t)phase * N_TOK + b) * PT_STRIDE;
    float mx = -1e30f, sm = 0.f;
    for (int t = lane; t < ntiles; t += 32) {
        float2 p = base[t];
        ol_merge(mx, sm, p.x, p.y);
    }
#pragma unroll
    for (int off = 16; off > 0; off >>= 1) {
        float om = __shfl_xor_sync(0xffffffff, mx, off);
        float os = __shfl_xor_sync(0xffffffff, sm, off);
        ol_merge(mx, sm, om, os);
    }
    if (lane == 0)
        d_nllv[phase * N_TOK + b] = logf(sm) + mx - d_labv[phase * N_TOK + b];
}

__global__ __launch_bounds__(1024)
void reduce_kernel(float* __restrict__ out) {
    __shared__ double s[1024];
    int c0 = min(d_cnt0, N_TOK), c1 = min(d_cnt1, N_TOK);
    double a = 0.0;
    for (int i = threadIdx.x; i < N_TOK; i += 1024) a += (double)d_nllv[i];
    for (int i = threadIdx.x; i < c0;    i += 1024) a += (double)d_nllv[N_TOK + i];
    for (int i = threadIdx.x; i < c1;    i += 1024) a += (double)d_nllv[2 * N_TOK + i];
    s[threadIdx.x] = a;
    __syncthreads();
#pragma unroll
    for (int k = 512; k > 0; k >>= 1) {
        if (threadIdx.x < k) s[threadIdx.x] += s[threadIdx.x + k];
        __syncthreads();
    }
    if (threadIdx.x == 0) out[0] = (float)(s[0] / (double)N_TOK);
}

// ---------------------------------------------------------------------------
extern "C" void kernel_launch(void* const* d_in, const int* in_sizes, int n_in,
                              void* d_out, int out_size) {
    const float* w_in   = (const float*)d_in[0];
    const int*   target = (const int*)d_in[1];
    const float* head_w = (const float*)d_in[2];
    const float* head_b = (const float*)d_in[3];
    const float* t0w1   = (const float*)d_in[4];
    const float* t0w2   = (const float*)d_in[5];
    const float* t1w1   = (const float*)d_in[6];
    const float* t1w2   = (const float*)d_in[7];
    float* out = (float*)d_out;

    init_kernel<<<1, 32>>>();
    gather_kernel<<<(N_TOK + 255) / 256, 256>>>(target);
    convert_kernel<<<(WTOT + 255) / 256, 256>>>(w_in, head_w, t0w1, t0w2,
                                                t1w1, t1w2);

    // stage A: head (fused CE) + t0s1 + t1s1
    gemm256<<<dim3(32, 32, 3), 256>>>(head_b, 0);
    // stage B: t1s2 (fused CE) + t0s2 (fused CE)
    gemm256<<<dim3(625, 32, 2), 256>>>(head_b, 1);

    ce_merge<<<dim3(N_TOK, 3), 32>>>();
    reduce_kernel<<<1, 1024>>>(out);
}

// round 17
// speedup vs baseline: 1.4916x; 1.0981x over previous
#include <cuda_runtime.h>
#include <cuda_fp16.h>
#include <cstdint>

// ---------------------------------------------------------------------------
// AdaptiveSoftmax — fp16 mma.sync, block 64x64 / warp 32x32 (6 blocks/SM,
// 4-warp barrier domains), 4-slot depth-3 cp.async ring, fused-CE epilogue.
//   0: w_in [4096,1024] f32   1: target [4096] i32
//   2: head_w [2002,1024] f32 3: head_b [2002] f32
//   4: tail0_w1 [1024,1024]   5: tail0_w2 [8000,1024]
//   6: tail1_w1 [256,1024]    7: tail1_w2 [40000,256]
//   out: scalar f32 loss
// ---------------------------------------------------------------------------

#define N_TOK 4096
#define PT_STRIDE 632   // >= 625 N-tiles (tail1, 64-wide)

// fp16 operands in kt32-tiled layout: u32 idx = ((kt*R + row)*16 + slot)
// slot(p) = (p&3)*4 + (p>>2) for kpair p in k-tile of 32 halves.
__device__ __align__(16) uint32_t d_winh [2097152];
__device__ __align__(16) uint32_t d_hwh  [1025024];
__device__ __align__(16) uint32_t d_t0w1h[524288];
__device__ __align__(16) uint32_t d_t0w2h[4096000];
__device__ __align__(16) uint32_t d_t1w1h[131072];
__device__ __align__(16) uint32_t d_t1w2h[5120000];
__device__ __align__(16) uint32_t d_h0h  [2097152];   // R=4096, K=1024
__device__ __align__(16) uint32_t d_h1h  [524288];    // R=4096, K=256

__device__ __align__(16) float2 d_part[(size_t)3 * N_TOK * PT_STRIDE];
__device__ float d_labv[3 * N_TOK];
__device__ float d_nllv[3 * N_TOK];
__device__ int   d_labh[N_TOK];
__device__ int   d_lab0[N_TOK];
__device__ int   d_lab1[N_TOK];
__device__ int   d_idx0[N_TOK];
__device__ int   d_idx1[N_TOK];
__device__ int   d_cnt0;
__device__ int   d_cnt1;

// ---------------------------------------------------------------------------
__global__ void init_kernel() {
    if (threadIdx.x == 0) { d_cnt0 = 0; d_cnt1 = 0; }
}

__global__ void gather_kernel(const int* __restrict__ target) {
    int i = blockIdx.x * blockDim.x + threadIdx.x;
    if (i >= N_TOK) return;
    int t = target[i];
    int labh = t;
    if (t >= 2000 && t < 10000) {
        labh = 2000;
        int p = atomicAdd(&d_cnt0, 1);
        if (p < N_TOK) { d_idx0[p] = i; d_lab0[p] = t - 2000; }
    } else if (t >= 10000 && t < 50000) {
        labh = 2001;
        int p = atomicAdd(&d_cnt1, 1);
        if (p < N_TOK) { d_idx1[p] = i; d_lab1[p] = t - 10000; }
    }
    d_labh[i] = min(max(labh, 0), 2001);
}

// ---------------------------------------------------------------------------
__device__ __forceinline__ uint32_t pack_h2(float x, float y) {
    __half2 h = __floats2half2_rn(x, y);
    return *reinterpret_cast<uint32_t*>(&h);
}

#define W0 524288
#define W1 256256
#define W2 131072
#define W3 1024000
#define W4 32768
#define W5 1280000
#define WTOT (W0+W1+W2+W3+W4+W5)

__global__ __launch_bounds__(256)
void convert_kernel(const float* __restrict__ w_in, const float* __restrict__ head_w,
                    const float* __restrict__ t0w1, const float* __restrict__ t0w2,
                    const float* __restrict__ t1w1, const float* __restrict__ t1w2) {
    int i = blockIdx.x * 256 + threadIdx.x;
    if (i >= WTOT) return;
    const float* src; uint32_t* dst; int R, K, c = i;
    if (c < W0)              { src = w_in;   dst = d_winh;  R = 4096;  K = 1024; }
    else if ((c -= W0) < W1) { src = head_w; dst = d_hwh;   R = 2002;  K = 1024; }
    else if ((c -= W1) < W2) { src = t0w1;   dst = d_t0w1h; R = 1024;  K = 1024; }
    else if ((c -= W2) < W3) { src = t0w2;   dst = d_t0w2h; R = 8000;  K = 1024; }
    else if ((c -= W3) < W4) { src = t1w1;   dst = d_t1w1h; R = 256;   K = 1024; }
    else      { c -= W4;       src = t1w2;   dst = d_t1w2h; R = 40000; K = 256;  }
    int nrow4 = R * 4;
    int kt = c / nrow4;
    int rem = c - kt * nrow4;
    int r = rem >> 2, g = rem & 3;
    const float* s = src + (size_t)r * K + kt * 32 + 2 * g;
    uint4 o;
    o.x = pack_h2(s[0],  s[1]);
    o.y = pack_h2(s[8],  s[9]);
    o.z = pack_h2(s[16], s[17]);
    o.w = pack_h2(s[24], s[25]);
    reinterpret_cast<uint4*>(dst)[((size_t)kt * R + r) * 4 + g] = o;
}

// ---------------------------------------------------------------------------
__device__ __forceinline__ void mma_f16(float* d, uint32_t a0, uint32_t a1,
                                        uint32_t a2, uint32_t a3,
                                        uint32_t b0, uint32_t b1) {
    asm volatile(
        "mma.sync.aligned.m16n8k16.row.col.f32.f16.f16.f32 "
        "{%0,%1,%2,%3}, {%4,%5,%6,%7}, {%8,%9}, {%0,%1,%2,%3};"
        : "+f"(d[0]), "+f"(d[1]), "+f"(d[2]), "+f"(d[3])
        : "r"(a0), "r"(a1), "r"(a2), "r"(a3), "r"(b0), "r"(b1));
}

__device__ __forceinline__ void cp16(uint32_t saddr, const void* g) {
    asm volatile("cp.async.cg.shared.global [%0], [%1], 16;"
                 :: "r"(saddr), "l"(g));
}
__device__ __forceinline__ void cp_commit() {
    asm volatile("cp.async.commit_group;" ::: "memory");
}
__device__ __forceinline__ void cp_wait2() {
    asm volatile("cp.async.wait_group 2;" ::: "memory");
}

__device__ __forceinline__ void ol_merge(float& mx, float& sm, float om, float os) {
    float nm = fmaxf(mx, om);
    sm = sm * __expf(mx - nm) + os * __expf(om - nm);
    mx = nm;
}

// ---------------------------------------------------------------------------
// Unified GEMM: block 64x64x32, 128 thr, 4 warps (2m x 2n), warp 32x32.
// Smem 32KB: A slot s at [s*4096 B], B slot s at [16384 + s*4096 B].
// 4-slot ring, depth-3 prefetch (wait_group 2), one 4-warp barrier per
// k-tile, x4-unrolled loop (compile-time slots). 6 blocks/SM.
// CE spart aliases slot 0 (nk%4==0 -> last tile in slot 3).
// ---------------------------------------------------------------------------
__global__ __launch_bounds__(128, 6)
void gemm128(const float* __restrict__ bias, int stage) {
    int z = blockIdx.z;
    const uint32_t *A, *Bw;
    uint32_t* Cout = nullptr;
    const int* idxArr = nullptr;
    const int* labArr = nullptr;
    int N, K, cnt, xmax, ce = 0, phase = 0;
    bool useBias = false;
    if (stage == 0) {
        if (z == 0)      { A = d_winh; Bw = d_hwh;   N = 2002; K = 1024; cnt = N_TOK;
                           xmax = 32; ce = 1; phase = 0; labArr = d_labh; useBias = true; }
        else if (z == 1) { A = d_winh; Bw = d_t0w1h; N = 1024; K = 1024; cnt = d_cnt0;
                           xmax = 16; idxArr = d_idx0; Cout = d_h0h; }
        else             { A = d_winh; Bw = d_t1w1h; N = 256;  K = 1024; cnt = d_cnt1;
                           xmax = 4; idxArr = d_idx1; Cout = d_h1h; }
    } else {
        if (z == 0)      { A = d_h1h; Bw = d_t1w2h; N = 40000; K = 256;  cnt = d_cnt1;
                           xmax = 625; ce = 1; phase = 2; labArr = d_lab1; }
        else             { A = d_h0h; Bw = d_t0w2h; N = 8000;  K = 1024; cnt = d_cnt0;
                           xmax = 125; ce = 1; phase = 1; labArr = d_lab0; }
    }
    if ((int)blockIdx.x >= xmax) return;
    if (cnt > N_TOK) cnt = N_TOK;
    int m0 = blockIdx.y * 64;
    int n0 = blockIdx.x * 64;
    if (m0 >= cnt) return;

    // 8192 u32 = 32KB: A slots [s*1024], B slots [4096 + s*1024]
    __shared__ __align__(16) uint32_t Smem[8192];
    float2 (*spart)[2] = reinterpret_cast<float2(*)[2]>(Smem);  // aliases slot A0

    int tid  = threadIdx.x;
    int lane = tid & 31;
    int warp = tid >> 5;
    int wm = warp & 1;       // m offset wm*32
    int wn = warp >> 1;      // n offset wn*32

    // ---- loaders: 2 threads/row (64 rows), 2 u4-chunks each, A and B ----
    int lrow = tid >> 1;
    int hh   = tid & 1;
    int g0 = 2 * hh, g1 = 2 * hh + 1;
    int swz = (lrow >> 1) & 3;
    uint32_t aSh = (uint32_t)__cvta_generic_to_shared(Smem);
    uint32_t dA0 = (lrow * 16 + 4 * (g0 ^ swz)) << 2;
    uint32_t dA1 = (lrow * 16 + 4 * (g1 ^ swz)) << 2;

    int am = m0 + lrow;
    int arow = (am < cnt) ? (idxArr ? idxArr[am] : am) : 0;
    arow = min(max(arow, 0), N_TOK - 1);
    int brow = min(n0 + lrow, N - 1);

    float acc[2][4][4];
#pragma unroll
    for (int mt = 0; mt < 2; mt++)
#pragma unroll
        for (int nt = 0; nt < 4; nt++)
#pragma unroll
            for (int e = 0; e < 4; e++) acc[mt][nt][e] = 0.0f;

    int gq = lane >> 2;
    int tq = lane & 3;

    // ---- fragment base offsets (loop-invariant, u32 units) ----
    uint32_t aOff[2][2], bOff[4];
#pragma unroll
    for (int mt = 0; mt < 2; mt++) {
        int ra = wm * 32 + mt * 16 + gq;
        aOff[mt][0] = (uint32_t)(ra * 16 + 4 * (tq ^ ((ra >> 1) & 3)));
        int rh = ra + 8;
        aOff[mt][1] = (uint32_t)(rh * 16 + 4 * (tq ^ ((rh >> 1) & 3)));
    }
#pragma unroll
    for (int nt = 0; nt < 4; nt++) {
        int rb = wn * 32 + nt * 8 + gq;
        bOff[nt] = (uint32_t)(rb * 16 + 4 * (tq ^ ((rb >> 1) & 3)));
    }

    int nk = K >> 5;
    const size_t aStep = 4096 * 16;          // u32 per A k-tile (R=4096)
    const size_t bStep = (size_t)N * 16;     // u32 per B k-tile
    const uint32_t* agp = A  + (size_t)arow * 16 + 4 * g0;
    const uint32_t* bgp = Bw + (size_t)brow * 16 + 4 * g0;

    // ---- prologue: tiles 0,1,2 -> slots 0,1,2 ----
#pragma unroll
    for (int p = 0; p < 3; p++) {
        uint32_t so = (uint32_t)p * 4096;
        cp16(aSh + so + dA0,         agp);
        cp16(aSh + so + dA1,         agp + 4);
        cp16(aSh + 16384 + so + dA0, bgp);
        cp16(aSh + 16384 + so + dA1, bgp + 4);
        cp_commit();
        agp += aStep; bgp += bStep;
    }

    for (int kt0 = 0; kt0 < nk; kt0 += 4) {
#pragma unroll
        for (int u = 0; u < 4; u++) {
            int kt = kt0 + u;
            cp_wait2();
            __syncthreads();
            if (kt + 3 < nk) {
                uint32_t so = (uint32_t)(((u + 3) & 3)) * 4096;
                cp16(aSh + so + dA0,         agp);
                cp16(aSh + so + dA1,         agp + 4);
                cp16(aSh + 16384 + so + dA0, bgp);
                cp16(aSh + 16384 + so + dA1, bgp + 4);
                agp += aStep; bgp += bStep;
            }
            cp_commit();

            const uint32_t* As = Smem + u * 1024;          // compile-time slot
            const uint32_t* Bs = Smem + 4096 + u * 1024;
            uint4 bf[4];
#pragma unroll
            for (int nt = 0; nt < 4; nt++)
                bf[nt] = *reinterpret_cast<const uint4*>(&Bs[bOff[nt]]);
#pragma unroll
            for (int mt = 0; mt < 2; mt++) {
                uint4 lo = *reinterpret_cast<const uint4*>(&As[aOff[mt][0]]);
                uint4 hi = *reinterpret_cast<const uint4*>(&As[aOff[mt][1]]);
#pragma unroll
                for (int nt = 0; nt < 4; nt++)
                    mma_f16(acc[mt][nt], lo.x, hi.x, lo.y, hi.y, bf[nt].x, bf[nt].y);
#pragma unroll
                for (int nt = 0; nt < 4; nt++)
                    mma_f16(acc[mt][nt], lo.z, hi.z, lo.w, hi.w, bf[nt].z, bf[nt].w);
            }
        }
    }

    if (ce) {
        // ---- fused CE epilogue ----
        float* labv = d_labv + phase * N_TOK;
#pragma unroll
        for (int mt = 0; mt < 2; mt++) {
#pragma unroll
            for (int h = 0; h < 2; h++) {
                int rloc = wm * 32 + mt * 16 + gq + h * 8;
                int m = m0 + rloc;
                bool ok = (m < cnt);
                int lab = ok ? labArr[m] : -1;
                float mx = -1e30f, sm = 0.f;
#pragma unroll
                for (int nt = 0; nt < 4; nt++) {
#pragma unroll
                    for (int e = 0; e < 2; e++) {
                        int col = n0 + wn * 32 + nt * 8 + tq * 2 + e;
                        if (col < N) {
                            float v = acc[mt][nt][h * 2 + e];
                            if (useBias) v += bias[col];
                            mx = fmaxf(mx, v);
                        }
                    }
                }
#pragma unroll
                for (int nt = 0; nt < 4; nt++) {
#pragma unroll
                    for (int e = 0; e < 2; e++) {
                        int col = n0 + wn * 32 + nt * 8 + tq * 2 + e;
                        if (col < N) {
                            float v = acc[mt][nt][h * 2 + e];
                            if (useBias) v += bias[col];
                            sm += __expf(v - mx);
                            if (ok && col == lab) labv[m] = v;
                        }
                    }
                }
#pragma unroll
                for (int off = 1; off <= 2; off <<= 1) {
                    float om = __shfl_xor_sync(0xffffffff, mx, off);
                    float os = __shfl_xor_sync(0xffffffff, sm, off);
                    ol_merge(mx, sm, om, os);
                }
                if (tq == 0) spart[rloc][wn] = make_float2(mx, sm);
            }
        }
        __syncthreads();
        if (tid < 64) {
            float mx = -1e30f, sm = 0.f;
#pragma unroll
            for (int w = 0; w < 2; w++) {
                float2 p = spart[tid][w];
                ol_merge(mx, sm, p.x, p.y);
            }
            int m = m0 + tid;
            if (m < cnt)
                d_part[((size_t)phase * N_TOK + m) * PT_STRIDE + blockIdx.x] =
                    make_float2(mx, sm);
        }
        return;
    }

    // ---- plain epilogue: write h in kt32-tiled fp16 layout ----
#pragma unroll
    for (int mt = 0; mt < 2; mt++) {
#pragma unroll
        for (int h = 0; h < 2; h++) {
            int r = m0 + wm * 32 + mt * 16 + gq + h * 8;
            if (r >= cnt) continue;
#pragma unroll
            for (int nt = 0; nt < 4; nt++) {
                int cb = n0 + wn * 32 + nt * 8 + tq * 2;
                int kt = cb >> 5;
                int p  = (cb & 31) >> 1;
                int s  = (p & 3) * 4 + (p >> 2);
                Cout[((size_t)kt * 4096 + r) * 16 + s] =
                    pack_h2(acc[mt][nt][h * 2 + 0], acc[mt][nt][h * 2 + 1]);
            }
        }
    }
}

// ---------------------------------------------------------------------------
__global__ __launch_bounds__(32)
void ce_merge() {
    int phase = blockIdx.y;
    int ntiles = (phase == 0) ? 32 : ((phase == 1) ? 125 : 625);
    int cnt    = (phase == 0) ? N_TOK : ((phase == 1) ? d_cnt0 : d_cnt1);
    if (cnt > N_TOK) cnt = N_TOK;
    int b = blockIdx.x;
    if (b >= cnt) return;
    int lane = threadIdx.x;

    const float2* base = d_part + ((size_t)phase * N_TOK + b) * PT_STRIDE;
    float mx = -1e30f, sm = 0.f;
    for (int t = lane; t < ntiles; t += 32) {
        float2 p = base[t];
        ol_merge(mx, sm, p.x, p.y);
    }
#pragma unroll
    for (int off = 16; off > 0; off >>= 1) {
        float om = __shfl_xor_sync(0xffffffff, mx, off);
        float os = __shfl_xor_sync(0xffffffff, sm, off);
        ol_merge(mx, sm, om, os);
    }
    if (lane == 0)
        d_nllv[phase * N_TOK + b] = logf(sm) + mx - d_labv[phase * N_TOK + b];
}

__global__ __launch_bounds__(1024)
void reduce_kernel(float* __restrict__ out) {
    __shared__ double s[1024];
    int c0 = min(d_cnt0, N_TOK), c1 = min(d_cnt1, N_TOK);
    double a = 0.0;
    for (int i = threadIdx.x; i < N_TOK; i += 1024) a += (double)d_nllv[i];
    for (int i = threadIdx.x; i < c0;    i += 1024) a += (double)d_nllv[N_TOK + i];
    for (int i = threadIdx.x; i < c1;    i += 1024) a += (double)d_nllv[2 * N_TOK + i];
    s[threadIdx.x] = a;
    __syncthreads();
#pragma unroll
    for (int k = 512; k > 0; k >>= 1) {
        if (threadIdx.x < k) s[threadIdx.x] += s[threadIdx.x + k];
        __syncthreads();
    }
    if (threadIdx.x == 0) out[0] = (float)(s[0] / (double)N_TOK);
}

// ---------------------------------------------------------------------------
extern "C" void kernel_launch(void* const* d_in, const int* in_sizes, int n_in,
                              void* d_out, int out_size) {
    const float* w_in   = (const float*)d_in[0];
    const int*   target = (const int*)d_in[1];
    const float* head_w = (const float*)d_in[2];
    const float* head_b = (const float*)d_in[3];
    const float* t0w1   = (const float*)d_in[4];
    const float* t0w2   = (const float*)d_in[5];
    const float* t1w1   = (const float*)d_in[6];
    const float* t1w2   = (const float*)d_in[7];
    float* out = (float*)d_out;

    init_kernel<<<1, 32>>>();
    gather_kernel<<<(N_TOK + 255) / 256, 256>>>(target);
    convert_kernel<<<(WTOT + 255) / 256, 256>>>(w_in, head_w, t0w1, t0w2,
                                                t1w1, t1w2);

    // stage A: head (fused CE) + t0s1 + t1s1
    gemm128<<<dim3(32, 64, 3), 128>>>(head_b, 0);
    // stage B: t1s2 (fused CE) + t0s2 (fused CE)
    gemm128<<<dim3(625, 64, 2), 128>>>(head_b, 1);

    ce_merge<<<dim3(N_TOK, 3), 32>>>();
    reduce_kernel<<<1, 1024>>>(out);
}